// round 15
// baseline (speedup 1.0000x reference)
#include <cuda_runtime.h>
#include <cuda_fp16.h>
#include <cstdint>

#define BB   32
#define NN   4096
#define CIN  128
#define COUT 128
#define MM   256
#define SPLITK_A 4

__device__ __forceinline__ uint32_t packh2(float lo, float hi) {
    uint32_t r;
    asm("cvt.rn.f16x2.f32 %0, %1, %2;" : "=r"(r) : "f"(hi), "f"(lo));
    return r;
}
__device__ __forceinline__ uint32_t smem_to_u32(const void* p) {
    uint32_t a;
    asm("{ .reg .u64 t; cvta.to.shared.u64 t, %1; cvt.u32.u64 %0, t; }" : "=r"(a) : "l"(p));
    return a;
}

// ===========================================================================
// Scratch (device globals — allocation-guard safe)
// ===========================================================================
__device__ __align__(16) __half g_Uh[NN * MM];                   // fp16 U   [n][m]
__device__ __align__(16) __half g_Uth[MM * NN];                  // fp16 U^T [m][n]
__device__ __align__(16) float  g_xsp[BB * SPLITK_A * MM * CIN]; // stage-A split-K partials
__device__ __align__(16) __half g_xsumh[MM * BB * CIN];          // folded, [m][b][c] fp16
__device__ __align__(16) __half g_wth[MM * COUT * CIN];          // [m][o][c] fp16
__device__ __align__(16) __half g_ospech[BB * COUT * MM];        // [b][o][m] fp16

// ===========================================================================
// kPrepU: U [n][m] fp32 -> g_Uh [n][m] fp16 and g_Uth [m][n] fp16
// ===========================================================================
__global__ __launch_bounds__(256) void kPrepU(const float* __restrict__ U) {
    __shared__ float t[32][33];
    const int n0 = blockIdx.x * 32, m0 = blockIdx.y * 32;
    const int tx = threadIdx.x, ty = threadIdx.y;
#pragma unroll
    for (int j = 0; j < 32; j += 8) {
        float v = U[(size_t)(n0 + ty + j) * MM + m0 + tx];
        t[ty + j][tx] = v;
        g_Uh[(size_t)(n0 + ty + j) * MM + m0 + tx] = __float2half_rn(v);
    }
    __syncthreads();
#pragma unroll
    for (int j = 0; j < 32; j += 8)
        g_Uth[(size_t)(m0 + ty + j) * NN + n0 + tx] = __float2half_rn(t[tx][ty + j]);
}

// ===========================================================================
// kT v2: W_real[c][o][m] -> g_wth[m][o][c] fp16 (side stream)
// Grid (COUT, CIN/32, MM/32): fixed o, 32x32 (c,m) tile, coalesced both sides.
// ===========================================================================
__global__ __launch_bounds__(256) void kT(const float* __restrict__ W) {
    __shared__ float tile[32][33];                 // [c][m]
    const int o = blockIdx.x, c0 = blockIdx.y * 32, m0 = blockIdx.z * 32;
    const int tx = threadIdx.x, ty = threadIdx.y;
#pragma unroll
    for (int j = 0; j < 32; j += 8)
        tile[ty + j][tx] = W[((size_t)(c0 + ty + j) * COUT + o) * MM + m0 + tx];
    __syncthreads();
#pragma unroll
    for (int j = 0; j < 32; j += 8)
        g_wth[((size_t)(m0 + ty + j) * COUT + o) * CIN + c0 + tx] =
            __float2half_rn(tile[tx][ty + j]);
}

// ===========================================================================
// Stage A GEMM (unchanged from R14): A fp16 [i][k] (U^T), B fp32 x cvt in-reg.
// CTA 128x128, 4 warps of 64x64, BK=32, double-buffered.
// ===========================================================================
#define A_BYTES (128 * 40 * 2)          // 10240
#define B_BYTES (32 * 132 * 4)          // 16896
#define BUF_BYTES (A_BYTES + B_BYTES)   // 27136
#define SMEM_G (2 * BUF_BYTES)          // 54272

template <int KCTA, int SPLITK>
__global__ __launch_bounds__(128, 2) void kGemmH(
    const __half* __restrict__ gA, const float* __restrict__ gB, float* __restrict__ gC,
    int lda, int ldb, int ldc, size_t strideB, size_t strideC)
{
    extern __shared__ char smc[];
    const uint32_t smU = smem_to_u32(smc);

    const int tid = threadIdx.x;
    const int w = tid >> 5, lane = tid & 31;
    const int m_w = (w & 1) * 64, j_w = (w >> 1) * 64;
    const int r4 = lane >> 2, c4 = lane & 3;

    const int i0 = blockIdx.x * 128;
    const int z  = blockIdx.z;
    const int b  = z / SPLITK;
    const int kbase = (z - b * SPLITK) * KCTA;
    const float* gBb = gB + (size_t)b * strideB;

    float acc[4][8][4];
#pragma unroll
    for (int mt = 0; mt < 4; mt++)
#pragma unroll
        for (int nt = 0; nt < 8; nt++)
#pragma unroll
            for (int q = 0; q < 4; q++) acc[mt][nt][q] = 0.f;

    auto load = [&](int k0, int buf) {
        const uint32_t base = smU + (uint32_t)(buf * BUF_BYTES);
#pragma unroll
        for (int it = 0; it < 4; it++) {
            int t4 = tid + it * 128;
            int rr = t4 >> 2, cc = t4 & 3;
            const __half* src = gA + (size_t)(i0 + rr) * lda + k0 + cc * 8;
            asm volatile("cp.async.cg.shared.global [%0], [%1], 16;"
                         :: "r"(base + (uint32_t)(rr * 80 + cc * 16)), "l"(src));
        }
#pragma unroll
        for (int it = 0; it < 8; it++) {
            int t4 = tid + it * 128;
            int kr = t4 >> 5, cc = t4 & 31;
            const float* src = gBb + (size_t)(k0 + kr) * ldb + cc * 4;
            asm volatile("cp.async.cg.shared.global [%0], [%1], 16;"
                         :: "r"(base + (uint32_t)(A_BYTES + kr * 528 + cc * 16)), "l"(src));
        }
        asm volatile("cp.async.commit_group;");
    };

    load(kbase, 0);
    constexpr int NCH = KCTA / 32;
    for (int ch = 0; ch < NCH; ch++) {
        const int buf = ch & 1;
        if (ch + 1 < NCH) {
            load(kbase + (ch + 1) * 32, buf ^ 1);
            asm volatile("cp.async.wait_group 1;");
        } else {
            asm volatile("cp.async.wait_group 0;");
        }
        __syncthreads();

        const char*  as = smc + buf * BUF_BYTES;
        const float* bs = (const float*)(as + A_BYTES);
#pragma unroll
        for (int kk = 0; kk < 32; kk += 16) {
            uint32_t a[4][4], bf[8][2];
#pragma unroll
            for (int mt = 0; mt < 4; mt++) {
                const int i = m_w + mt * 16 + r4;
                const int hbase = i * 40 + kk + 2 * c4;
                a[mt][0] = *(const uint32_t*)(as + (size_t)hbase * 2);
                a[mt][1] = *(const uint32_t*)(as + (size_t)(hbase + 320) * 2);
                a[mt][2] = *(const uint32_t*)(as + (size_t)(hbase + 8) * 2);
                a[mt][3] = *(const uint32_t*)(as + (size_t)(hbase + 328) * 2);
            }
#pragma unroll
            for (int nt = 0; nt < 8; nt++) {
                const int n = j_w + nt * 8 + r4;
                const float* p0 = bs + (kk + 2 * c4) * 132 + n;
                bf[nt][0] = packh2(p0[0],       p0[132]);
                bf[nt][1] = packh2(p0[8 * 132], p0[9 * 132]);
            }
#pragma unroll
            for (int mt = 0; mt < 4; mt++)
#pragma unroll
                for (int nt = 0; nt < 8; nt++)
                    asm volatile(
                        "mma.sync.aligned.m16n8k16.row.col.f32.f16.f16.f32 "
                        "{%0,%1,%2,%3}, {%4,%5,%6,%7}, {%8,%9}, {%0,%1,%2,%3};"
                        : "+f"(acc[mt][nt][0]), "+f"(acc[mt][nt][1]),
                          "+f"(acc[mt][nt][2]), "+f"(acc[mt][nt][3])
                        : "r"(a[mt][0]), "r"(a[mt][1]), "r"(a[mt][2]), "r"(a[mt][3]),
                          "r"(bf[nt][0]), "r"(bf[nt][1]));
        }
        __syncthreads();
    }

    float* cb = gC + (size_t)z * strideC;
#pragma unroll
    for (int mt = 0; mt < 4; mt++)
#pragma unroll
        for (int nt = 0; nt < 8; nt++) {
            const int r = i0 + m_w + mt * 16 + r4;
            const int c = j_w + nt * 8 + c4 * 2;
            float2 v0 = { acc[mt][nt][0], acc[mt][nt][1] };
            float2 v1 = { acc[mt][nt][2], acc[mt][nt][3] };
            *(float2*)&cb[(size_t)r * ldc + c] = v0;
            *(float2*)&cb[(size_t)(r + 8) * ldc + c] = v1;
        }
}

// ===========================================================================
// Stage C GEMM: A fp16 [n][m] (U), B fp16 ospech [b][o][m] = col-major [j][k].
// CTA 128(n) x 128(o), BK=32(m), no cvt in loop, B tile fp16.
// ===========================================================================
#define C_ABYTES (128 * 40 * 2)           // 10240
#define C_BBYTES (128 * 40 * 2)           // 10240
#define C_BUF (C_ABYTES + C_BBYTES)       // 20480
#define SMEM_GC2 (2 * C_BUF)              // 40960

__global__ __launch_bounds__(128, 2) void kGemmC(
    const __half* __restrict__ gA, const __half* __restrict__ gB, float* __restrict__ gC)
{
    extern __shared__ char smc[];
    const uint32_t smU = smem_to_u32(smc);

    const int tid = threadIdx.x;
    const int w = tid >> 5, lane = tid & 31;
    const int m_w = (w & 1) * 64, j_w = (w >> 1) * 64;
    const int r4 = lane >> 2, c4 = lane & 3;

    const int i0 = blockIdx.x * 128;
    const int b  = blockIdx.z;
    const __half* gBb = gB + (size_t)b * COUT * MM;   // [o][m]

    float acc[4][8][4];
#pragma unroll
    for (int mt = 0; mt < 4; mt++)
#pragma unroll
        for (int nt = 0; nt < 8; nt++)
#pragma unroll
            for (int q = 0; q < 4; q++) acc[mt][nt][q] = 0.f;

    auto load = [&](int k0, int buf) {
        const uint32_t base = smU + (uint32_t)(buf * C_BUF);
#pragma unroll
        for (int it = 0; it < 4; it++) {            // A: 128 rows x 64 B
            int t4 = tid + it * 128;
            int rr = t4 >> 2, cc = t4 & 3;
            const __half* src = gA + (size_t)(i0 + rr) * MM + k0 + cc * 8;
            asm volatile("cp.async.cg.shared.global [%0], [%1], 16;"
                         :: "r"(base + (uint32_t)(rr * 80 + cc * 16)), "l"(src));
        }
#pragma unroll
        for (int it = 0; it < 4; it++) {            // B: 128 o-rows x 64 B
            int t4 = tid + it * 128;
            int rr = t4 >> 2, cc = t4 & 3;
            const __half* src = gBb + (size_t)rr * MM + k0 + cc * 8;
            asm volatile("cp.async.cg.shared.global [%0], [%1], 16;"
                         :: "r"(base + (uint32_t)(C_ABYTES + rr * 80 + cc * 16)), "l"(src));
        }
        asm volatile("cp.async.commit_group;");
    };

    load(0, 0);
    constexpr int NCH = MM / 32;
    for (int ch = 0; ch < NCH; ch++) {
        const int buf = ch & 1;
        if (ch + 1 < NCH) {
            load((ch + 1) * 32, buf ^ 1);
            asm volatile("cp.async.wait_group 1;");
        } else {
            asm volatile("cp.async.wait_group 0;");
        }
        __syncthreads();

        const char* as = smc + buf * C_BUF;
        const char* bs = as + C_ABYTES;
#pragma unroll
        for (int kk = 0; kk < 32; kk += 16) {
            uint32_t a[4][4], bf[8][2];
#pragma unroll
            for (int mt = 0; mt < 4; mt++) {
                const int i = m_w + mt * 16 + r4;
                const int hbase = i * 40 + kk + 2 * c4;
                a[mt][0] = *(const uint32_t*)(as + (size_t)hbase * 2);
                a[mt][1] = *(const uint32_t*)(as + (size_t)(hbase + 320) * 2);
                a[mt][2] = *(const uint32_t*)(as + (size_t)(hbase + 8) * 2);
                a[mt][3] = *(const uint32_t*)(as + (size_t)(hbase + 328) * 2);
            }
#pragma unroll
            for (int nt = 0; nt < 8; nt++) {
                const int n = j_w + nt * 8 + r4;
                const int hbase = n * 40 + kk + 2 * c4;
                bf[nt][0] = *(const uint32_t*)(bs + (size_t)hbase * 2);
                bf[nt][1] = *(const uint32_t*)(bs + (size_t)(hbase + 8) * 2);
            }
#pragma unroll
            for (int mt = 0; mt < 4; mt++)
#pragma unroll
                for (int nt = 0; nt < 8; nt++)
                    asm volatile(
                        "mma.sync.aligned.m16n8k16.row.col.f32.f16.f16.f32 "
                        "{%0,%1,%2,%3}, {%4,%5,%6,%7}, {%8,%9}, {%0,%1,%2,%3};"
                        : "+f"(acc[mt][nt][0]), "+f"(acc[mt][nt][1]),
                          "+f"(acc[mt][nt][2]), "+f"(acc[mt][nt][3])
                        : "r"(a[mt][0]), "r"(a[mt][1]), "r"(a[mt][2]), "r"(a[mt][3]),
                          "r"(bf[nt][0]), "r"(bf[nt][1]));
        }
        __syncthreads();
    }

    float* cb = gC + (size_t)b * NN * COUT;
#pragma unroll
    for (int mt = 0; mt < 4; mt++)
#pragma unroll
        for (int nt = 0; nt < 8; nt++) {
            const int r = i0 + m_w + mt * 16 + r4;
            const int c = j_w + nt * 8 + c4 * 2;
            float2 v0 = { acc[mt][nt][0], acc[mt][nt][1] };
            float2 v1 = { acc[mt][nt][2], acc[mt][nt][3] };
            *(float2*)&cb[(size_t)r * COUT + c] = v0;
            *(float2*)&cb[(size_t)(r + 8) * COUT + c] = v1;
        }
}

// ===========================================================================
// kFold v2: g_xsumh[m][b][c] = fp16(sum_s xsp[b][s][m][c]), 8 floats/thread
// ===========================================================================
__global__ __launch_bounds__(256) void kFold() {
    const int id = blockIdx.x * 256 + threadIdx.x;   // 131072 ids
    const int m   = id >> 9;
    const int rem = id & 511;
    const int b   = rem >> 4;
    const int c8  = (rem & 15) * 8;

    const float* base = g_xsp + (((size_t)b * SPLITK_A) * MM + m) * CIN + c8;
    float4 v0 = *(const float4*)base;
    float4 v1 = *(const float4*)(base + 4);
#pragma unroll
    for (int s = 1; s < SPLITK_A; s++) {
        const float* p = base + (size_t)s * MM * CIN;
        float4 p0 = *(const float4*)p;
        float4 p1 = *(const float4*)(p + 4);
        v0.x += p0.x; v0.y += p0.y; v0.z += p0.z; v0.w += p0.w;
        v1.x += p1.x; v1.y += p1.y; v1.z += p1.z; v1.w += p1.w;
    }
    uint4 out;
    out.x = packh2(v0.x, v0.y);
    out.y = packh2(v0.z, v0.w);
    out.z = packh2(v1.x, v1.y);
    out.w = packh2(v1.z, v1.w);
    *(uint4*)&g_xsumh[(((size_t)m * BB) + b) * CIN + c8] = out;
}

// ===========================================================================
// kB3 v3 (fp16 MMA): ospech[b][o][m] = sum_c wth[m][o][c] * xsumh[m][b][c]
//   i=o (from wth, row-major [i][k]), j=b (xsumh = col-major [j][k]), k=c.
//   Grid (MM, 2 o-halves) = 512 CTAs, 8 warps: 4(o) x 2(b), 16x16 per warp.
// ===========================================================================
#define B3_PAD 136                         // halves per row (128 + 8)
#define B3_ABYTES (64 * B3_PAD * 2)        // 17408
#define B3_BBYTES (32 * B3_PAD * 2)        // 8704

__global__ __launch_bounds__(256) void kB3() {
    __shared__ char smB[B3_ABYTES + B3_BBYTES];
    char* as = smB;
    char* bs = smB + B3_ABYTES;
    const uint32_t aU = smem_to_u32(as);
    const uint32_t bU = smem_to_u32(bs);

    const int m = blockIdx.x;
    const int h = blockIdx.y;
    const int t = threadIdx.x;
    const int w = t >> 5, lane = t & 31;
    const int r4 = lane >> 2, c4 = lane & 3;
    const int m_w = (w & 3) * 16;       // o-offset of warp within half
    const int j_w = (w >> 2) * 16;      // b-offset of warp

    // A: wth[m] rows o = h*64 .. +64, 128 c halves (256 B rows)
    const __half* am = g_wth + ((size_t)m * COUT + h * 64) * CIN;
#pragma unroll
    for (int it = 0; it < 4; it++) {
        int t4 = t + it * 256;          // 0..1023
        int rr = t4 >> 4, cc = t4 & 15;
        asm volatile("cp.async.cg.shared.global [%0], [%1], 16;"
                     :: "r"(aU + (uint32_t)(rr * (B3_PAD * 2) + cc * 16)),
                        "l"(am + (size_t)rr * CIN + cc * 8));
    }
    // B: xsumh[m] 32 b-rows x 128 c halves
    const __half* xm = g_xsumh + (size_t)m * BB * CIN;
#pragma unroll
    for (int it = 0; it < 2; it++) {
        int t4 = t + it * 256;          // 0..511
        int rr = t4 >> 4, cc = t4 & 15;
        asm volatile("cp.async.cg.shared.global [%0], [%1], 16;"
                     :: "r"(bU + (uint32_t)(rr * (B3_PAD * 2) + cc * 16)),
                        "l"(xm + (size_t)rr * CIN + cc * 8));
    }
    asm volatile("cp.async.commit_group;");
    asm volatile("cp.async.wait_group 0;");
    __syncthreads();

    float acc[2][4];
#pragma unroll
    for (int nt = 0; nt < 2; nt++)
#pragma unroll
        for (int q = 0; q < 4; q++) acc[nt][q] = 0.f;

#pragma unroll
    for (int kk = 0; kk < CIN; kk += 16) {
        const int iA = m_w + r4;
        const int ha = iA * B3_PAD + kk + 2 * c4;
        uint32_t a0 = *(const uint32_t*)(as + (size_t)ha * 2);
        uint32_t a1 = *(const uint32_t*)(as + (size_t)(ha + 8 * B3_PAD) * 2);
        uint32_t a2 = *(const uint32_t*)(as + (size_t)(ha + 8) * 2);
        uint32_t a3 = *(const uint32_t*)(as + (size_t)(ha + 8 * B3_PAD + 8) * 2);
#pragma unroll
        for (int nt = 0; nt < 2; nt++) {
            const int jB = j_w + nt * 8 + r4;
            const int hb = jB * B3_PAD + kk + 2 * c4;
            uint32_t b0 = *(const uint32_t*)(bs + (size_t)hb * 2);
            uint32_t b1 = *(const uint32_t*)(bs + (size_t)(hb + 8) * 2);
            asm volatile(
                "mma.sync.aligned.m16n8k16.row.col.f32.f16.f16.f32 "
                "{%0,%1,%2,%3}, {%4,%5,%6,%7}, {%8,%9}, {%0,%1,%2,%3};"
                : "+f"(acc[nt][0]), "+f"(acc[nt][1]), "+f"(acc[nt][2]), "+f"(acc[nt][3])
                : "r"(a0), "r"(a1), "r"(a2), "r"(a3), "r"(b0), "r"(b1));
        }
    }

    // Epilogue: C[i=o][j=b] -> ospech[b][o][m] fp16 (scattered STG.16)
#pragma unroll
    for (int nt = 0; nt < 2; nt++) {
        const int o0 = h * 64 + m_w + r4;
        const int b0 = j_w + nt * 8 + 2 * c4;
        g_ospech[((size_t)b0 * COUT + o0) * MM + m]            = __float2half_rn(acc[nt][0]);
        g_ospech[((size_t)(b0 + 1) * COUT + o0) * MM + m]      = __float2half_rn(acc[nt][1]);
        g_ospech[((size_t)b0 * COUT + o0 + 8) * MM + m]        = __float2half_rn(acc[nt][2]);
        g_ospech[((size_t)(b0 + 1) * COUT + o0 + 8) * MM + m]  = __float2half_rn(acc[nt][3]);
    }
}

// ===========================================================================
// Launch — kT on side stream concurrent with prepU + stage A + fold.
// ===========================================================================
extern "C" void kernel_launch(void* const* d_in, const int* in_sizes, int n_in,
                              void* d_out, int out_size) {
    const float* x = (const float*)d_in[0];   // [32,4096,128]
    const float* U = (const float*)d_in[1];   // [4096,256]
    const float* W = (const float*)d_in[2];   // [128,128,256] (W_imag d_in[3] is dead)
    float* out = (float*)d_out;               // [32,4096,128]

    float*  dxsp; cudaGetSymbolAddress((void**)&dxsp, g_xsp);
    __half* dUh;  cudaGetSymbolAddress((void**)&dUh,  g_Uh);
    __half* dUth; cudaGetSymbolAddress((void**)&dUth, g_Uth);
    __half* dosh; cudaGetSymbolAddress((void**)&dosh, g_ospech);

    cudaFuncSetAttribute((const void*)kGemmH<NN / SPLITK_A, SPLITK_A>,
                         cudaFuncAttributeMaxDynamicSharedMemorySize, SMEM_G);
    cudaFuncSetAttribute((const void*)kGemmC,
                         cudaFuncAttributeMaxDynamicSharedMemorySize, SMEM_GC2);

    static cudaStream_t s1 = nullptr;
    static cudaEvent_t eFork = nullptr, eT = nullptr;
    if (s1 == nullptr) {
        cudaStreamCreateWithFlags(&s1, cudaStreamNonBlocking);
        cudaEventCreateWithFlags(&eFork, cudaEventDisableTiming);
        cudaEventCreateWithFlags(&eT, cudaEventDisableTiming);
    }

    // Fork: kT on s1, concurrent with prepU + stage A on the main stream.
    cudaEventRecord(eFork, 0);
    cudaStreamWaitEvent(s1, eFork, 0);
    kT<<<dim3(COUT, CIN / 32, MM / 32), dim3(32, 8), 0, s1>>>(W);
    cudaEventRecord(eT, s1);

    // U -> fp16 (straight + transposed)
    kPrepU<<<dim3(NN / 32, MM / 32), dim3(32, 8)>>>(U);

    // Stage A: xsp partials = U^T @ x per batch-slice.  A = g_Uth [m][n] fp16.
    kGemmH<NN / SPLITK_A, SPLITK_A>
        <<<dim3(MM / 128, 1, BB * SPLITK_A), 128, SMEM_G>>>(
            dUth, x, dxsp, NN, CIN, CIN, (size_t)NN * CIN, (size_t)MM * CIN);

    // Fold split-K partials -> fp16 [m][b][c]
    kFold<<<512, 256>>>();

    // Join: kB3 needs g_wth from kT.
    cudaStreamWaitEvent(0, eT, 0);

    // Stage B: per-mode channel mix, pure fp16 MMA
    kB3<<<dim3(MM, 2), 256>>>();

    // Stage C: out = U @ ospec per batch. A = g_Uh fp16, B = ospech fp16.
    kGemmC<<<dim3(NN / 128, 1, BB), 128, SMEM_GC2>>>(dUh, dosh, out);
}